// round 17
// baseline (speedup 1.0000x reference)
#include <cuda_runtime.h>
#include <cuda_bf16.h>

// Fixed problem shape
#define Nn 128
#define Tt 1024
#define TM 512            // fwd owns t=0..511, bwd owns t=512..1023
#define Cc 256
#define Ll 128
#define NEGV    (-1e30f)
#define INV_LN2 1.4426950408889634f
#define LN2     0.6931471805599453f
#define NOTRDY  (1e30f)
#define RSTG 16
#define PAD 8             // alpha/beta smem pad (k = s + 8)

__device__ float g_losses[Nn];

// ---------------------------------------------------------------------------
__device__ __forceinline__ float ex2f_(float x) {
    float y; asm("ex2.approx.ftz.f32 %0, %1;" : "=f"(y) : "f"(x)); return y;
}
__device__ __forceinline__ float lg2f_(float x) {
    float y; asm("lg2.approx.ftz.f32 %0, %1;" : "=f"(y) : "f"(x)); return y;
}
__device__ __forceinline__ float ld_acq_f(const float* p) {
    unsigned a = (unsigned)__cvta_generic_to_shared((const void*)p);
    int v; asm volatile("ld.acquire.cta.shared.b32 %0, [%1];"
                        : "=r"(v) : "r"(a) : "memory");
    return __int_as_float(v);
}
__device__ __forceinline__ void st_rel_f(float* p, float v) {
    unsigned a = (unsigned)__cvta_generic_to_shared((void*)p);
    asm volatile("st.release.cta.shared.b32 [%0], %1;"
                 :: "r"(a), "r"(__float_as_int(v)) : "memory");
}
__device__ __forceinline__ int ld_acq_i(const int* p) {
    unsigned a = (unsigned)__cvta_generic_to_shared((const void*)p);
    int v; asm volatile("ld.acquire.cta.shared.b32 %0, [%1];"
                        : "=r"(v) : "r"(a) : "memory");
    return v;
}
__device__ __forceinline__ void st_rel_i(int* p, int v) {
    unsigned a = (unsigned)__cvta_generic_to_shared((void*)p);
    asm volatile("st.release.cta.shared.b32 [%0], %1;"
                 :: "r"(a), "r"(v) : "memory");
}
__device__ __forceinline__ float pollf(const float* p) {
    float v = ld_acq_f(p);
    while (v > 1e29f) v = ld_acq_f(p);
    return v;
}
__device__ __forceinline__ float lse2c_(float a, float b, float lp) {
    float m = fmaxf(a, b);
    return fmaxf(m + lg2f_(ex2f_(a - m) + ex2f_(b - m)) + lp, NEGV);
}
#define BARF() asm volatile("bar.sync 1, 128;" ::: "memory")
#define BARB() asm volatile("bar.sync 2, 128;" ::: "memory")
#define BARC() asm volatile("bar.sync 3, 256;" ::: "memory")

// forward pair: even s=2k (stay,step), odd s=2k+1 (stay,step,skip)
__device__ __forceinline__ float2 fpair(float aEm1, float aE0, float aO0,
                                        bool sk, float lpB, float lpL) {
    float m  = fmaxf(fmaxf(aE0, aEm1), aO0);
    float e0 = ex2f_(aE0 - m), e1 = ex2f_(aEm1 - m), e2 = ex2f_(aO0 - m);
    float rE = fmaxf(m + lg2f_(e0 + e1) + lpB, NEGV);
    float rO = fmaxf(m + lg2f_(e2 + e0 + (sk ? e1 : 0.f)) + lpL, NEGV);
    return make_float2(rE, rO);
}
// backward pair k: even s=2k reads beta[2k,2k+1]; odd reads [2k+1,2k+2,(2k+3)]
__device__ __forceinline__ float2 bpair(float2 w0, float2 w1,
                                        bool skb, float lpB, float lpL) {
    float bS = skb ? w1.y : NEGV;
    float m  = fmaxf(fmaxf(w0.x, w0.y), fmaxf(w1.x, bS));
    float e0 = ex2f_(w0.x - m), e1 = ex2f_(w0.y - m), e2 = ex2f_(w1.x - m);
    float e3 = skb ? ex2f_(bS - m) : 0.f;
    float rE = fmaxf(m + lg2f_(e0 + e1)      + lpB, NEGV);
    float rO = fmaxf(m + lg2f_(e1 + e2 + e3) + lpL, NEGV);
    return make_float2(rE, rO);
}

// ---------------------------------------------------------------------------
// One block per batch element n. 512 threads (16 warps).
// QUAD-STEPPED barrier recursion: per barrier, 4 time steps via redundant
// halo pairs (fwd: pairs i-3..i @t+1, i-2..i @t+2, i-1..i @t+3, i @t+4;
// bwd mirrored upward with a locally-recomputed beta[256] self-loop chain).
// 511 steps = one 3-step block + 127 quad blocks per direction.
// warps 0-3 fwd recursion / 4-7 bwd recursion / 8-11 fwd prod / 12-15 bwd prod.
// ---------------------------------------------------------------------------
__global__ void __launch_bounds__(512) ctc_fused(const float* __restrict__ preds,
                                                 const int*   __restrict__ targets) {
    __shared__ int   s_tg[Ll];
    __shared__ float s_lpb[Tt];
    __shared__ __align__(16) float glpF[RSTG][Ll];
    __shared__ __align__(16) float glpB[RSTG][Ll];
    __shared__ __align__(16) float rowF[4][Cc];
    __shared__ __align__(16) float rowB[4][Cc];
    __shared__ __align__(16) float As[2][280];   // k=s+8; s=0..255 @ k=8..263
    __shared__ __align__(16) float Bs[2][280];   // + beta[256] @ k=264
    __shared__ float red[8];
    __shared__ int s_tdF, s_tdB;

    const int n    = blockIdx.x;
    const int tid  = threadIdx.x;
    const int wid  = tid >> 5;
    const int lane = tid & 31;
    const int grp  = tid >> 7;
    const size_t base = (size_t)n * Tt * Cc;

    int tgv = (tid < Ll) ? targets[n * Ll + tid] : 0;
    if (tid < Ll) s_tg[tid] = tgv;
    for (int k = tid; k < Tt; k += 512) s_lpb[k] = NOTRDY;
    for (int k = tid; k < 2 * 280; k += 512) {
        (&As[0][0])[k] = NEGV; (&Bs[0][0])[k] = NEGV;
    }
    if (tid == 0) { s_tdF = -1; s_tdB = Tt; }
    const int tl = __syncthreads_count(tgv != 0);

    // ======================= producers =======================
    if (grp >= 2) {
        const bool fwd = (grp == 2);
        const int  w   = wid & 3;
        float* rbuf = fwd ? rowF[w] : rowB[w];
        const float4* p4 = (const float4*)(preds + base);
        int c0 = s_tg[4 * lane], c1 = s_tg[4 * lane + 1],
            c2 = s_tg[4 * lane + 2], c3 = s_tg[4 * lane + 3];

        int t0  = fwd ? w : (Tt - 1 - w);
        int stp = fwd ? 4 : -4;

        float4 f0 = __ldg(p4 + (size_t)t0 * 64 + lane);
        float4 f1 = __ldg(p4 + (size_t)t0 * 64 + lane + 32);
        float4 g0 = __ldg(p4 + (size_t)(t0 + stp) * 64 + lane);
        float4 g1 = __ldg(p4 + (size_t)(t0 + stp) * 64 + lane + 32);

        for (int t = t0; fwd ? (t < TM) : (t >= TM); t += stp) {
            int t2 = t + 2 * stp;
            float4 h0, h1;
            bool okp = fwd ? (t2 < TM) : (t2 >= TM);
            if (okp) {
                h0 = __ldg(p4 + (size_t)t2 * 64 + lane);
                h1 = __ldg(p4 + (size_t)t2 * 64 + lane + 32);
            }
            if (fwd) { if (t >= RSTG)          while (ld_acq_i(&s_tdF) + 11 < t) { } }
            else     { if (t <= Tt - 1 - RSTG) while (ld_acq_i(&s_tdB) - 11 > t) { } }

            float4* dst = (float4*)rbuf;
            dst[lane] = f0; dst[lane + 32] = f1;
            __syncwarp();

            float S = ex2f_(f0.x * INV_LN2) + ex2f_(f0.y * INV_LN2)
                    + ex2f_(f0.z * INV_LN2) + ex2f_(f0.w * INV_LN2)
                    + ex2f_(f1.x * INV_LN2) + ex2f_(f1.y * INV_LN2)
                    + ex2f_(f1.z * INV_LN2) + ex2f_(f1.w * INV_LN2);
#pragma unroll
            for (int o = 16; o; o >>= 1) S += __shfl_xor_sync(0xffffffffu, S, o);
            float l2 = lg2f_(S);

            float4 q;
            q.x = __fmaf_rn(rbuf[c0], INV_LN2, -l2);
            q.y = __fmaf_rn(rbuf[c1], INV_LN2, -l2);
            q.z = __fmaf_rn(rbuf[c2], INV_LN2, -l2);
            q.w = __fmaf_rn(rbuf[c3], INV_LN2, -l2);
            float* grow = fwd ? glpF[t & (RSTG - 1)] : glpB[t & (RSTG - 1)];
            ((float4*)grow)[lane] = q;
            __syncwarp();
            if (lane == 0)
                st_rel_f(&s_lpb[t], __fmaf_rn(f0.x, INV_LN2, -l2));

            f0 = g0; f1 = g1; g0 = h0; g1 = h1;
        }
        return;
    }

    if (grp == 0) {
        // ======================= forward (quad-stepped) =======================
        const int i  = tid;
        const int i1 = (i > 0) ? i - 1 : 0;
        const int i2 = (i > 1) ? i - 2 : 0;
        const int i3 = (i > 2) ? i - 3 : 0;
        int tg0  = s_tg[i];
        int tgm1 = (i > 0) ? s_tg[i - 1] : 0;
        int tgm2 = (i > 1) ? s_tg[i - 2] : 0;
        int tgm3 = (i > 2) ? s_tg[i - 3] : 0;
        int tgm4 = (i > 3) ? s_tg[i - 4] : 0;
        const bool sk0 = tg0  && (tg0  != tgm1);
        const bool sk1 = tgm1 && (tgm1 != tgm2);
        const bool sk2 = tgm2 && (tgm2 != tgm3);
        const bool sk3 = tgm3 && (tgm3 != tgm4);
        const bool tail = (i == 127);

        float lpB1, lpB2, lpB3, lpB4;
        float lpL1_0, lpL1_1, lpL1_2, lpL1_3, lpL2_0, lpL2_1, lpL2_2,
              lpL3_0, lpL3_1, lpL4_0;
        float a256 = NEGV;

        // alpha_0 into As[0]
        {
            float lpB0 = pollf(&s_lpb[0]);
            float lpL0 = glpF[0][0];
            ((float2*)&As[0][PAD])[i] = (i == 0) ? make_float2(lpB0, lpL0)
                                                 : make_float2(NEGV, NEGV);
        }
        // prefetch for 3-step block (t=1,2,3)
        lpB1 = pollf(&s_lpb[1]); lpL1_0 = glpF[1][i]; lpL1_1 = glpF[1][i1]; lpL1_2 = glpF[1][i2];
        lpB2 = pollf(&s_lpb[2]); lpL2_0 = glpF[2][i]; lpL2_1 = glpF[2][i1];
        lpB3 = pollf(&s_lpb[3]); lpL3_0 = glpF[3][i];
        BARF();

        // 3-step block: alpha_0 -> alpha_3 (As[1])
        {
            const float2* src = (const float2*)&As[0][0];
            float2 w1 = src[i + 1], w2 = src[i + 2], w3 = src[i + 3], w4 = src[i + 4];
            float2 p2v = fpair(w1.y, w2.x, w2.y, sk2, lpB1, lpL1_2);
            float2 p1v = fpair(w2.y, w3.x, w3.y, sk1, lpB1, lpL1_1);
            float2 p0v = fpair(w3.y, w4.x, w4.y, sk0, lpB1, lpL1_0);
            float2 q1v = fpair(p2v.y, p1v.x, p1v.y, sk1, lpB2, lpL2_1);
            float2 q0v = fpair(p1v.y, p0v.x, p0v.y, sk0, lpB2, lpL2_0);
            float2 r0v = fpair(q1v.y, q0v.x, q0v.y, sk0, lpB3, lpL3_0);
            ((float2*)&As[1][PAD])[i] = r0v;
            if (tail) {
                a256 = lse2c_(a256, w4.y,  lpB1);
                a256 = lse2c_(a256, p0v.y, lpB2);
                a256 = lse2c_(a256, q0v.y, lpB3);
            }
        }
        // prefetch first quad (t=4..7)
        lpB1 = pollf(&s_lpb[4]); lpL1_0 = glpF[4][i]; lpL1_1 = glpF[4][i1];
        lpL1_2 = glpF[4][i2]; lpL1_3 = glpF[4][i3];
        lpB2 = pollf(&s_lpb[5]); lpL2_0 = glpF[5][i]; lpL2_1 = glpF[5][i1]; lpL2_2 = glpF[5][i2];
        lpB3 = pollf(&s_lpb[6]); lpL3_0 = glpF[6][i]; lpL3_1 = glpF[6][i1];
        lpB4 = pollf(&s_lpb[7]); lpL4_0 = glpF[7][i];
        if (tid == 0) st_rel_i(&s_tdF, 3);
        BARF();

        int p = 1;
        for (int t = 4; t < TM; t += 4) {        // 127 quad blocks -> alpha_511
            const int c = p ^ 1;
            const float2* src = (const float2*)&As[p][0];
            float2 w0 = src[i],     w1 = src[i + 1], w2 = src[i + 2],
                   w3 = src[i + 3], w4 = src[i + 4];

            float2 pm3 = fpair(w0.y, w1.x, w1.y, sk3, lpB1, lpL1_3);
            float2 pm2 = fpair(w1.y, w2.x, w2.y, sk2, lpB1, lpL1_2);
            float2 pm1 = fpair(w2.y, w3.x, w3.y, sk1, lpB1, lpL1_1);
            float2 pm0 = fpair(w3.y, w4.x, w4.y, sk0, lpB1, lpL1_0);
            float2 qm2 = fpair(pm3.y, pm2.x, pm2.y, sk2, lpB2, lpL2_2);
            float2 qm1 = fpair(pm2.y, pm1.x, pm1.y, sk1, lpB2, lpL2_1);
            float2 qm0 = fpair(pm1.y, pm0.x, pm0.y, sk0, lpB2, lpL2_0);
            float2 rm1 = fpair(qm2.y, qm1.x, qm1.y, sk1, lpB3, lpL3_1);
            float2 rm0 = fpair(qm1.y, qm0.x, qm0.y, sk0, lpB3, lpL3_0);
            float2 sm0 = fpair(rm1.y, rm0.x, rm0.y, sk0, lpB4, lpL4_0);
            ((float2*)&As[c][PAD])[i] = sm0;
            if (tail) {
                a256 = lse2c_(a256, w4.y,  lpB1);
                a256 = lse2c_(a256, pm0.y, lpB2);
                a256 = lse2c_(a256, qm0.y, lpB3);
                a256 = lse2c_(a256, rm0.y, lpB4);
            }
            p = c;

            int ta = (t + 4 < TM) ? t + 4 : TM - 1;
            int tb = (t + 5 < TM) ? t + 5 : TM - 1;
            int tc = (t + 6 < TM) ? t + 6 : TM - 1;
            int td = (t + 7 < TM) ? t + 7 : TM - 1;
            lpB1 = pollf(&s_lpb[ta]); lpL1_0 = glpF[ta & 15][i]; lpL1_1 = glpF[ta & 15][i1];
            lpL1_2 = glpF[ta & 15][i2]; lpL1_3 = glpF[ta & 15][i3];
            lpB2 = pollf(&s_lpb[tb]); lpL2_0 = glpF[tb & 15][i]; lpL2_1 = glpF[tb & 15][i1];
            lpL2_2 = glpF[tb & 15][i2];
            lpB3 = pollf(&s_lpb[tc]); lpL3_0 = glpF[tc & 15][i]; lpL3_1 = glpF[tc & 15][i1];
            lpB4 = pollf(&s_lpb[td]); lpL4_0 = glpF[td & 15][i];
            if (tid == 0) st_rel_i(&s_tdF, t + 3);
            BARF();
        }
        // alpha_511 in As[0]

        BARC();   // beta~_512 ready in Bs[1]

        // ---- combine ----
        {
            const float2* src = (const float2*)&As[0][0];
            float2 w3 = src[i + 3], w4 = src[i + 4];
            float aEm1 = w3.y, aE0 = w4.x, aO0 = w4.y;
            float2 B2 = ((const float2*)&Bs[1][PAD])[i];

            float m  = fmaxf(fmaxf(aE0, aEm1), aO0);
            float e0 = ex2f_(aE0 - m), e1 = ex2f_(aEm1 - m), e2 = ex2f_(aO0 - m);
            float vE = m + lg2f_(e0 + e1)                   + B2.x;
            float vO = m + lg2f_(e2 + e0 + (sk0 ? e1 : 0.f)) + B2.y;

            float M = fmaxf(vE, vO);
            float E = ex2f_(vE - M) + ex2f_(vO - M);
            if (tail) {
                float mT = fmaxf(a256, aO0);
                float v256 = mT + lg2f_(ex2f_(a256 - mT) + ex2f_(aO0 - mT)) + Bs[1][264];
                float nm = fmaxf(M, v256);
                E = E * ex2f_(M - nm) + ex2f_(v256 - nm);
                M = nm;
            }
#pragma unroll
            for (int o = 16; o; o >>= 1) {
                float om = __shfl_xor_sync(0xffffffffu, M, o);
                float oe = __shfl_xor_sync(0xffffffffu, E, o);
                float nm = fmaxf(M, om);
                E = E * ex2f_(M - nm) + oe * ex2f_(om - nm);
                M = nm;
            }
            if (lane == 0) { red[2 * wid] = M; red[2 * wid + 1] = E; }
            BARF();
            if (tid == 0) {
                float Mf = red[0], Ef = red[1];
#pragma unroll
                for (int wv = 1; wv < 4; ++wv) {
                    float om = red[2 * wv], oe = red[2 * wv + 1];
                    float nm = fmaxf(Mf, om);
                    Ef = Ef * ex2f_(Mf - nm) + oe * ex2f_(om - nm);
                    Mf = nm;
                }
                float fin  = (Mf + lg2f_(Ef)) * LN2;
                float loss = (fin < -1e29f) ? 0.0f : -fin;
                int tld = (tl > 0) ? tl : 1;
                g_losses[n] = loss / (float)tld;
            }
        }
        return;
    }

    // ======================= backward (quad-stepped) =======================
    {
        const int j  = tid - 128;
        const int j1 = (j < 127) ? j + 1 : 127;
        const int j2 = (j < 126) ? j + 2 : 127;
        const int j3 = (j < 125) ? j + 3 : 127;
        int tj0 = s_tg[j];
        int tj1 = (j + 1 < Ll) ? s_tg[j + 1] : 0;
        int tj2 = (j + 2 < Ll) ? s_tg[j + 2] : 0;
        int tj3 = (j + 3 < Ll) ? s_tg[j + 3] : 0;
        int tj4 = (j + 4 < Ll) ? s_tg[j + 4] : 0;
        const bool kb0 = tj1 && (tj1 != tj0);
        const bool kb1 = tj2 && (tj2 != tj1);
        const bool kb2 = tj3 && (tj3 != tj2);
        const bool kb3 = tj4 && (tj4 != tj3);

        float lpB1, lpB2, lpB3, lpB4;
        float lpL1_0, lpL1_1, lpL1_2, lpL1_3, lpL2_0, lpL2_1, lpL2_2,
              lpL3_0, lpL3_1, lpL4_0;

        // beta_1023 into Bs[1]
        {
            float lpB0 = pollf(&s_lpb[Tt - 1]);
            float lpO0 = glpB[(Tt - 1) & 15][j];
            float2 b;
            b.x = (j == tl)     ? lpB0 : NEGV;
            b.y = (j == tl - 1) ? lpO0 : NEGV;
            ((float2*)&Bs[1][PAD])[j] = b;
            if (j == 127) Bs[1][264] = (tl == Ll || tl == 0) ? lpB0 : NEGV;
        }
        // prefetch 3-step block (t=1022,1021,1020)
        lpB1 = pollf(&s_lpb[1022]); lpL1_0 = glpB[1022 & 15][j]; lpL1_1 = glpB[1022 & 15][j1];
        lpL1_2 = glpB[1022 & 15][j2];
        lpB2 = pollf(&s_lpb[1021]); lpL2_0 = glpB[1021 & 15][j]; lpL2_1 = glpB[1021 & 15][j1];
        lpB3 = pollf(&s_lpb[1020]); lpL3_0 = glpB[1020 & 15][j];
        BARB();

        // 3-step block: beta_1023 -> beta_1020 (Bs[0])
        {
            const float2* src = (const float2*)&Bs[1][0];
            float2 w0 = src[j + 4], w1 = src[j + 5], w2 = src[j + 6], w3 = src[j + 7];
            float B256 = Bs[1][264];
            float b1 = fmaxf(B256 + lpB1, NEGV);
            float b2 = fmaxf(b1 + lpB2, NEGV);
            float b3 = fmaxf(b2 + lpB3, NEGV);

            float2 u0 = bpair(w0, w1, kb0, lpB1, lpL1_0);
            float2 u1 = bpair(w1, w2, kb1, lpB1, lpL1_1);
            float2 u2 = bpair(w2, w3, kb2, lpB1, lpL1_2);
            if (j + 1 >= 128) u1 = (j + 1 == 128) ? make_float2(b1, NEGV) : make_float2(NEGV, NEGV);
            if (j + 2 >= 128) u2 = (j + 2 == 128) ? make_float2(b1, NEGV) : make_float2(NEGV, NEGV);

            float2 v0 = bpair(u0, u1, kb0, lpB2, lpL2_0);
            float2 v1 = bpair(u1, u2, kb1, lpB2, lpL2_1);
            if (j + 1 >= 128) v1 = (j + 1 == 128) ? make_float2(b2, NEGV) : make_float2(NEGV, NEGV);

            float2 y0 = bpair(v0, v1, kb0, lpB3, lpL3_0);
            ((float2*)&Bs[0][PAD])[j] = y0;
            if (j == 127) Bs[0][264] = b3;
        }
        // prefetch first quad (t=1019..1016)
        lpB1 = pollf(&s_lpb[1019]); lpL1_0 = glpB[1019 & 15][j]; lpL1_1 = glpB[1019 & 15][j1];
        lpL1_2 = glpB[1019 & 15][j2]; lpL1_3 = glpB[1019 & 15][j3];
        lpB2 = pollf(&s_lpb[1018]); lpL2_0 = glpB[1018 & 15][j]; lpL2_1 = glpB[1018 & 15][j1];
        lpL2_2 = glpB[1018 & 15][j2];
        lpB3 = pollf(&s_lpb[1017]); lpL3_0 = glpB[1017 & 15][j]; lpL3_1 = glpB[1017 & 15][j1];
        lpB4 = pollf(&s_lpb[1016]); lpL4_0 = glpB[1016 & 15][j];
        if (tid == 128) st_rel_i(&s_tdB, 1020);
        BARB();

        int p = 0;
        for (int t = 1019; t >= TM; t -= 4) {    // 127 quad blocks -> beta_512
            const int c = p ^ 1;
            const float2* src = (const float2*)&Bs[p][0];
            float2 w0 = src[j + 4], w1 = src[j + 5], w2 = src[j + 6],
                   w3 = src[j + 7], w4 = src[j + 8];
            float B256 = Bs[p][264];
            float b1 = fmaxf(B256 + lpB1, NEGV);
            float b2 = fmaxf(b1 + lpB2, NEGV);
            float b3 = fmaxf(b2 + lpB3, NEGV);
            float b4 = fmaxf(b3 + lpB4, NEGV);

            float2 u0 = bpair(w0, w1, kb0, lpB1, lpL1_0);
            float2 u1 = bpair(w1, w2, kb1, lpB1, lpL1_1);
            float2 u2 = bpair(w2, w3, kb2, lpB1, lpL1_2);
            float2 u3 = bpair(w3, w4, kb3, lpB1, lpL1_3);
            if (j + 1 >= 128) u1 = (j + 1 == 128) ? make_float2(b1, NEGV) : make_float2(NEGV, NEGV);
            if (j + 2 >= 128) u2 = (j + 2 == 128) ? make_float2(b1, NEGV) : make_float2(NEGV, NEGV);
            if (j + 3 >= 128) u3 = (j + 3 == 128) ? make_float2(b1, NEGV) : make_float2(NEGV, NEGV);

            float2 v0 = bpair(u0, u1, kb0, lpB2, lpL2_0);
            float2 v1 = bpair(u1, u2, kb1, lpB2, lpL2_1);
            float2 v2 = bpair(u2, u3, kb2, lpB2, lpL2_2);
            if (j + 1 >= 128) v1 = (j + 1 == 128) ? make_float2(b2, NEGV) : make_float2(NEGV, NEGV);
            if (j + 2 >= 128) v2 = (j + 2 == 128) ? make_float2(b2, NEGV) : make_float2(NEGV, NEGV);

            float2 x0 = bpair(v0, v1, kb0, lpB3, lpL3_0);
            float2 x1 = bpair(v1, v2, kb1, lpB3, lpL3_1);
            if (j + 1 >= 128) x1 = (j + 1 == 128) ? make_float2(b3, NEGV) : make_float2(NEGV, NEGV);

            float2 y0 = bpair(x0, x1, kb0, lpB4, lpL4_0);
            ((float2*)&Bs[c][PAD])[j] = y0;
            if (j == 127) Bs[c][264] = b4;
            p = c;

            int ta = (t - 4 >= TM) ? t - 4 : TM;
            int tb = (t - 5 >= TM) ? t - 5 : TM;
            int tc = (t - 6 >= TM) ? t - 6 : TM;
            int td = (t - 7 >= TM) ? t - 7 : TM;
            lpB1 = pollf(&s_lpb[ta]); lpL1_0 = glpB[ta & 15][j]; lpL1_1 = glpB[ta & 15][j1];
            lpL1_2 = glpB[ta & 15][j2]; lpL1_3 = glpB[ta & 15][j3];
            lpB2 = pollf(&s_lpb[tb]); lpL2_0 = glpB[tb & 15][j]; lpL2_1 = glpB[tb & 15][j1];
            lpL2_2 = glpB[tb & 15][j2];
            lpB3 = pollf(&s_lpb[tc]); lpL3_0 = glpB[tc & 15][j]; lpL3_1 = glpB[tc & 15][j1];
            lpB4 = pollf(&s_lpb[td]); lpL4_0 = glpB[td & 15][j];
            if (tid == 128) st_rel_i(&s_tdB, t - 3);
            BARB();
        }
        // beta_512 in Bs[1]
        BARC();
        return;
    }
}

// ---------------------------------------------------------------------------
__global__ void __launch_bounds__(128) reduce_kernel(float* __restrict__ out) {
    int tid = threadIdx.x;
    float v = g_losses[tid];
#pragma unroll
    for (int o = 16; o; o >>= 1) v += __shfl_xor_sync(0xffffffffu, v, o);
    __shared__ float sm[4];
    if ((tid & 31) == 0) sm[tid >> 5] = v;
    __syncthreads();
    if (tid == 0) out[0] = (sm[0] + sm[1] + sm[2] + sm[3]) * (1.0f / (float)Nn);
}

// ---------------------------------------------------------------------------
extern "C" void kernel_launch(void* const* d_in, const int* in_sizes, int n_in,
                              void* d_out, int out_size) {
    const float* preds;
    const int*   targets;
    if (in_sizes[0] == Nn * Tt * Cc) {
        preds   = (const float*)d_in[0];
        targets = (const int*)  d_in[1];
    } else {
        preds   = (const float*)d_in[1];
        targets = (const int*)  d_in[0];
    }
    float* out = (float*)d_out;

    ctc_fused   <<<Nn, 512>>>(preds, targets);
    reduce_kernel<<<1, 128>>>(out);
}